// round 17
// baseline (speedup 1.0000x reference)
#include <cuda_runtime.h>
#include <math.h>

// Device-global accumulators. g_sum starts 0 (static init); finalize resets it
// after reading so every graph replay sees 0. g_loss_r overwritten every launch.
__device__ double g_sum = 0.0;
__device__ float  g_loss_r = 0.0f;

// ---------------------------------------------------------------------------
// Grid distance: nearest cell (round-half-even = jnp.round), integer clamp.
// Gather 12B via ONE 16B-aligned LDG.128 (+ predicated LDG.64 tail for 50% of
// offsets). IEEE sqrtf on purpose (approx-MUFU measured slower, R13/R14).
// ---------------------------------------------------------------------------
__device__ __forceinline__ float grid_dist(float tx, float ty, float tz,
                                           const float* __restrict__ grid,
                                           const float2* __restrict__ grid2,
                                           const float4* __restrict__ grid4,
                                           float bx, float by, float bz,
                                           float sx, float sy, float sz,
                                           int Rm1, unsigned strideX, unsigned strideY)
{
    int ix = __float2int_rn(fmaf(tx, sx, bx));
    int iy = __float2int_rn(fmaf(ty, sy, by));
    int iz = __float2int_rn(fmaf(tz, sz, bz));
    ix = min(max(ix, 0), Rm1);
    iy = min(max(iy, 0), Rm1);
    iz = min(max(iz, 0), Rm1);
    unsigned off = (unsigned)ix * strideX + (unsigned)iy * strideY + (unsigned)iz * 3u;

    unsigned q = off >> 2;         // float4 index
    unsigned r = off & 3u;         // position within the float4
    float4 v = __ldg(grid4 + q);

    float ex = 0.f, ey = 0.f;
    if (r >= 2u) {                 // tail crosses the 16B boundary
        float2 e = __ldg(grid2 + (q + 1u) * 2u);   // floats base+4, base+5
        ex = e.x; ey = e.y;
    }

    // r=0: (v.x,v.y,v.z)  r=1: (v.y,v.z,v.w)  r=2: (v.z,v.w,ex)  r=3: (v.w,ex,ey)
    bool ge2 = (r >= 2u);
    bool odd = (r & 1u) != 0u;
    float c0 = ge2 ? (odd ? v.w : v.z) : (odd ? v.y : v.x);
    float c1 = ge2 ? (odd ? ex  : v.w) : (odd ? v.z : v.y);
    float c2 = ge2 ? (odd ? ey  : ex ) : (odd ? v.w : v.z);

    float dx = tx - c0, dy = ty - c1, dz = tz - c2;
    return sqrtf(fmaf(dx, dx, fmaf(dy, dy, dz * dz)));
}

// ---------------------------------------------------------------------------
// All 6 transforms + gathers for one point.
// ---------------------------------------------------------------------------
__device__ __forceinline__ float point_loss(float px, float py, float pz,
                                            const float4* __restrict__ planes4,
                                            const float4* __restrict__ axes4,
                                            const float* __restrict__ grid,
                                            const float2* __restrict__ grid2,
                                            const float4* __restrict__ grid4,
                                            float bx, float by, float bz,
                                            float sx, float sy, float sz,
                                            int Rm1, unsigned strideX, unsigned strideY)
{
    float acc = 0.f;

    #pragma unroll
    for (int k = 0; k < 3; k++) {
        float4 pl = __ldg(planes4 + k);
        float proj = px * pl.x + py * pl.y + pz * pl.z + pl.w;
        float rx = px - 2.f * proj * pl.x;
        float ry = py - 2.f * proj * pl.y;
        float rz = pz - 2.f * proj * pl.z;
        acc += grid_dist(rx, ry, rz, grid, grid2, grid4,
                         bx, by, bz, sx, sy, sz, Rm1, strideX, strideY);
    }

    #pragma unroll
    for (int k = 0; k < 3; k++) {
        float4 q = __ldg(axes4 + k);
        float w = q.x, x = q.y, y = q.z, z = q.w;
        float tw = -x * px - y * py - z * pz;
        float qx =  w * px + y * pz - z * py;
        float qy =  w * py - x * pz + z * px;
        float qz =  w * pz + x * py - y * px;
        float rx = -tw * x + qx * w - qy * z + qz * y;
        float ry = -tw * y + qx * z + qy * w - qz * x;
        float rz = -tw * z - qx * y + qy * x + qz * w;
        acc += grid_dist(rx, ry, rz, grid, grid2, grid4,
                         bx, by, bz, sx, sy, sz, Rm1, strideX, strideY);
    }

    return acc;
}

// ---------------------------------------------------------------------------
// Persistent main kernel: 6 blocks/SM * 148 SMs, grid-stride (~4.4 iters),
// one block reduction + one double atomic per block. Point loads use __ldcs.
// ---------------------------------------------------------------------------
__global__ void __launch_bounds__(256, 6)
main_kernel(const float* __restrict__ pts,
            const float4* __restrict__ planes4,
            const float4* __restrict__ axes4,
            const float* __restrict__ grid,
            const float* __restrict__ gmin,
            const float* __restrict__ gmax,
            int N, int R)
{
    const float2* __restrict__ grid2 = (const float2*)grid;
    const float4* __restrict__ grid4 = (const float4*)grid;

    float gx = __ldg(gmin), gy = __ldg(gmin + 1), gz = __ldg(gmin + 2);
    float sx = (float)(R - 1) / (__ldg(gmax)     - gx);
    float sy = (float)(R - 1) / (__ldg(gmax + 1) - gy);
    float sz = (float)(R - 1) / (__ldg(gmax + 2) - gz);
    float bx = -gx * sx, by = -gy * sy, bz = -gz * sz;
    unsigned strideY = (unsigned)(R * 3);
    unsigned strideX = strideY * (unsigned)R;
    int Rm1 = R - 1;

    int tid     = blockIdx.x * blockDim.x + threadIdx.x;
    int nthread = gridDim.x * blockDim.x;

    float local = 0.f;

    for (int i = tid; i < N; i += nthread) {
        float px = __ldcs(pts + 3 * i);        // streaming: read-once data
        float py = __ldcs(pts + 3 * i + 1);
        float pz = __ldcs(pts + 3 * i + 2);
        local += point_loss(px, py, pz, planes4, axes4, grid, grid2, grid4,
                            bx, by, bz, sx, sy, sz, Rm1, strideX, strideY);
    }

    // Warp reduce
    #pragma unroll
    for (int off = 16; off > 0; off >>= 1)
        local += __shfl_down_sync(0xFFFFFFFFu, local, off);

    // Block reduce
    __shared__ float warp_sums[8];
    int lane = threadIdx.x & 31;
    int wid  = threadIdx.x >> 5;
    if (lane == 0) warp_sums[wid] = local;
    __syncthreads();
    if (wid == 0) {
        float s = (lane < 8) ? warp_sums[lane] : 0.f;
        #pragma unroll
        for (int off = 4; off > 0; off >>= 1)
            s += __shfl_down_sync(0xFFFFFFFFu, s, off);
        if (lane == 0)
            atomicAdd(&g_sum, (double)s);
    }

    // Regularizer (independent of the reduction): one thread computes it.
    if (blockIdx.x == 0 && threadIdx.x == 0) {
        float n[3][3], v[3][3];
        #pragma unroll
        for (int r = 0; r < 3; r++) {
            float4 pl = __ldg(planes4 + r);
            n[r][0] = pl.x; n[r][1] = pl.y; n[r][2] = pl.z;
            float4 q = __ldg(axes4 + r);
            float nrm = sqrtf(q.y * q.y + q.z * q.z + q.w * q.w);
            float inv = 1.f / fmaxf(nrm, 1e-12f);
            v[r][0] = q.y * inv; v[r][1] = q.z * inv; v[r][2] = q.w * inv;
        }
        float sumA2 = 0.f, sumB2 = 0.f;
        #pragma unroll
        for (int r = 0; r < 3; r++)
            #pragma unroll
            for (int c = 0; c < 3; c++) {
                float da = n[r][0] * n[c][0] + n[r][1] * n[c][1] + n[r][2] * n[c][2]
                         - (r == c ? 1.f : 0.f);
                float db = v[r][0] * v[c][0] + v[r][1] * v[c][1] + v[r][2] * v[c][2]
                         - (r == c ? 1.f : 0.f);
                sumA2 += da * da;
                sumB2 += db * db;
            }
        g_loss_r = sumA2 + sumB2;
    }
}

// ---------------------------------------------------------------------------
// Finalize (1 thread): read accumulators, write outputs, reset for replay.
// ---------------------------------------------------------------------------
__global__ void finalize_kernel(float* __restrict__ out, int out_size, int N)
{
    double total = g_sum;
    g_sum = 0.0;   // reset for next graph replay
    float loss_r = g_loss_r;

    float sd  = (float)(total / (double)N);
    float fin = sd + 25.0f * loss_r;
    out[0] = fin;
    if (out_size > 1) out[1] = sd;
    if (out_size > 2) out[2] = loss_r;
}

// ---------------------------------------------------------------------------
extern "C" void kernel_launch(void* const* d_in, const int* in_sizes, int n_in,
                              void* d_out, int out_size)
{
    const float* planes = (const float*)d_in[0];   // (1,3,4)
    const float* axes   = (const float*)d_in[1];   // (1,3,4)
    const float* pts    = (const float*)d_in[2];   // (N,3)
    const float* grid   = (const float*)d_in[3];   // (R,R,R,3)
    const float* gmin   = (const float*)d_in[4];   // (3,)
    const float* gmax   = (const float*)d_in[5];   // (3,)

    int N = in_sizes[2] / 3;
    long gelems = (long)in_sizes[3] / 3;
    int R = (int)llrintf(cbrtf((float)gelems));

    // Persistent: fill the chip exactly — 6 blocks/SM * 148 SMs.
    int threads = 256;
    int blocks  = 6 * 148;
    int maxBlocks = (N + threads - 1) / threads;
    if (blocks > maxBlocks) blocks = maxBlocks;

    main_kernel<<<blocks, threads>>>(pts, (const float4*)planes,
                                     (const float4*)axes, grid, gmin, gmax, N, R);
    finalize_kernel<<<1, 1>>>((float*)d_out, out_size, N);
}